// round 16
// baseline (speedup 1.0000x reference)
#include <cuda_runtime.h>
#include <cuda_bf16.h>
#include <cuda_fp16.h>
#include <mma.h>
#include <cstdint>
#include <math.h>

using namespace nvcuda;

// Problem constants (fixed instance)
#define NN    8192
#define BB    32
#define NMAX  512
#define FF    128
#define HH    512
#define LL    3
#define GG    8
#define HFF   2048
#define EE    131072
#define HG    (HH/GG)    // 64
#define HFG   (HFF/GG)   // 256
#define ADJW  16
#define ADJTOT ((size_t)BB*NMAX*ADJW)

#define FLAG_SIG 2

// fp16 GEMM tiling: 128xBN block tile, BK=64, 3-stage cp.async
#define BM    128
#define BK64  64
#define LDA_E 72     // half elems/row (144B) -> ldmatrix conflict-free

typedef __half half_t;

// -------------------- scratch (device globals; no allocs) --------------------
__device__ __align__(16) float g_h  [NN*HH];
__device__ __align__(16) float g_out[NN*HH];
__device__ float    g_deg[NN];
__device__ int      g_starts[BB+1];
__device__ int      g_pos[NN];
__device__ unsigned g_adj[ADJTOT];
// fp16 operands
__device__ __align__(16) half_t g_xh  [NN*FF];
__device__ __align__(16) half_t g_hgh [NN*HH];
__device__ __align__(16) half_t g_qkh [NN*HH];
__device__ __align__(16) half_t g_atth[NN*HH];
__device__ __align__(16) half_t g_hnh [NN*HH];
__device__ __align__(16) half_t g_uph [NN*HFF];
__device__ __align__(16) half_t g_dnh [NN*HH];
__device__ __align__(16) half_t g_Winh[FF*HH];
__device__ __align__(16) half_t g_Wqkh[LL*HH*HH];
__device__ __align__(16) half_t g_Wlh [LL*HH*HH];
__device__ __align__(16) half_t g_Wrh [LL*HH*HH];
__device__ __align__(16) half_t g_upwh[LL*GG*HG*HFG];
__device__ __align__(16) half_t g_dnwh[LL*GG*HFG*HG];

__device__ __forceinline__ float sigf(float x){ return 1.f/(1.f+__expf(-x)); }

__device__ __forceinline__ void cpa16(uint32_t s, const void* g){
    asm volatile("cp.async.cg.shared.global [%0], [%1], 16;" :: "r"(s), "l"(g));
}
__device__ __forceinline__ void cpa_commit(){ asm volatile("cp.async.commit_group;"); }
template<int N> __device__ __forceinline__ void cpa_wait(){
    asm volatile("cp.async.wait_group %0;" :: "n"(N));
}
__device__ __forceinline__ uint32_t smem_u32(const void* p){
    uint32_t a;
    asm("{ .reg .u64 t; cvta.to.shared.u64 t, %1; cvt.u32.u64 %0, t; }" : "=r"(a) : "l"(p));
    return a;
}

// -------------------- fp32 -> fp16 (rn) bulk convert --------------------
__global__ void convert_k(const float* __restrict__ src, half_t* __restrict__ dst, int n){
    int i = (blockIdx.x*blockDim.x + threadIdx.x) * 4;
    if (i >= n) return;
    float4 v = *(const float4*)(src + i);
    __half2 p0 = __floats2half2_rn(v.x, v.y);
    __half2 p1 = __floats2half2_rn(v.z, v.w);
    *(uint2*)(dst + i) = make_uint2(*(uint32_t*)&p0, *(uint32_t*)&p1);
}

// -------------------- graph structure --------------------
__global__ void clear_adj_k(unsigned* __restrict__ adj, float* __restrict__ outz){
    size_t i = (size_t)blockIdx.x*blockDim.x + threadIdx.x;
    if (i < ADJTOT) adj[i] = 0u;
    if (i < BB*HH) outz[i] = 0.f;
}
__global__ void starts_k(const int* __restrict__ batch, int* __restrict__ starts){
    int n = blockIdx.x*blockDim.x + threadIdx.x;
    if (n >= NN) return;
    if (n == 0){ starts[batch[0]] = 0; starts[BB] = NN; }
    else if (batch[n] != batch[n-1]) starts[batch[n]] = n;
}
__global__ void pos_self_k(const int* __restrict__ batch, const int* __restrict__ starts,
                           int* __restrict__ pos, unsigned* __restrict__ adj){
    int n = blockIdx.x*blockDim.x + threadIdx.x;
    if (n >= NN) return;
    int b = batch[n];
    int p = n - starts[b];
    pos[n] = p;
    atomicOr(&adj[((size_t)b*NMAX + p)*ADJW + (p>>5)], 1u << (p&31));
}
__global__ void edge_k(const int* __restrict__ ei, const int* __restrict__ batch,
                       const int* __restrict__ pos, unsigned* __restrict__ adj){
    int e = blockIdx.x*blockDim.x + threadIdx.x;
    if (e >= EE) return;
    int s = ei[e];
    int d = ei[EE + e];
    int b = batch[s];
    atomicOr(&adj[((size_t)b*NMAX + pos[s])*ADJW + (pos[d]>>5)], 1u << (pos[d]&31));
}
__global__ void deg_k(const int* __restrict__ batch, const int* __restrict__ pos,
                      const unsigned* __restrict__ adj, float* __restrict__ deg){
    int n = blockIdx.x*blockDim.x + threadIdx.x;
    if (n >= NN) return;
    const unsigned* row = adj + ((size_t)batch[n]*NMAX + pos[n])*ADJW;
    int c = 0;
    #pragma unroll
    for (int w = 0; w < ADJW; w++) c += __popc(row[w]);
    deg[n] = (float)c;
}

// -------------------- fp16 tensor-core GEMM (unified) ------------------------
template<int BN_, bool DUAL, bool HOUT>
__global__ void __launch_bounds__(256, 2)
gemm_h(const half_t* __restrict__ A, int lda, long long sAz,
       const half_t* __restrict__ W, int ldw, long long sWz,
       const half_t* __restrict__ A2, const half_t* __restrict__ W2,
       void* __restrict__ Cv, int ldc, long long sCz,
       const float* __restrict__ bias, long long sBz,
       int K, int flags)
{
    constexpr int LDB_E = BN_ + 8;
    constexpr int LDC_  = BN_ + 4;
    constexpr int ASZB  = BM * LDA_E * 2;
    constexpr int BSZB  = BK64 * LDB_E * 2;
    constexpr int STGB  = ASZB + BSZB;
    constexpr int NF    = BN_ / 32;
    constexpr int BROW8 = BN_ / 8;
    constexpr int BCH   = (BK64 * BROW8) / 256;

    A += (size_t)blockIdx.z * sAz;
    W += (size_t)blockIdx.z * sWz;
    size_t czoff = (size_t)blockIdx.z * sCz;
    bias += (size_t)blockIdx.z * sBz;

    extern __shared__ __align__(16) char smc[];

    int tid  = threadIdx.x;
    int warp = tid >> 5;
    int wm   = warp >> 1;
    int wn   = warp & 1;
    int row0 = blockIdx.y * BM;
    int col0 = blockIdx.x * BN_;

    wmma::fragment<wmma::accumulator, 16, 16, 16, float> acc[2][NF];
    #pragma unroll
    for (int i = 0; i < 2; i++)
        #pragma unroll
        for (int j = 0; j < NF; j++)
            wmma::fill_fragment(acc[i][j], 0.0f);

    const int T  = K / BK64;
    const int TT = DUAL ? 2*T : T;

    auto prefetch = [&](int j){
        const half_t* Ap = (DUAL && j >= T) ? A2 : A;
        const half_t* Wp = (DUAL && j >= T) ? W2 : W;
        int k0 = (DUAL ? (j % T) : j) * BK64;
        uint32_t a0 = smem_u32(smc + (j % 3)*STGB);
        uint32_t b0 = a0 + ASZB;
        #pragma unroll
        for (int i = 0; i < 4; i++){
            int f = tid + i*256, r = f >> 3, c = f & 7;
            cpa16(a0 + r*(LDA_E*2) + c*16, Ap + (size_t)(row0+r)*lda + k0 + c*8);
        }
        #pragma unroll
        for (int i = 0; i < BCH; i++){
            int f = tid + i*256, r = f / BROW8, c = f % BROW8;
            cpa16(b0 + r*(LDB_E*2) + c*16, Wp + (size_t)(k0+r)*ldw + col0 + c*8);
        }
        cpa_commit();
    };

    prefetch(0);
    if (TT > 1) prefetch(1);

    for (int it = 0; it < TT; it++){
        if (it + 1 < TT) cpa_wait<1>(); else cpa_wait<0>();
        __syncthreads();
        if (it + 2 < TT) prefetch(it + 2);

        half_t* As = (half_t*)(smc + (it % 3)*STGB);
        half_t* Bs = (half_t*)(smc + (it % 3)*STGB + ASZB);
        #pragma unroll
        for (int kk = 0; kk < BK64; kk += 16){
            wmma::fragment<wmma::matrix_a, 16, 16, 16, half_t, wmma::row_major> fa[2];
            wmma::fragment<wmma::matrix_b, 16, 16, 16, half_t, wmma::row_major> fb[NF];
            #pragma unroll
            for (int i = 0; i < 2; i++)
                wmma::load_matrix_sync(fa[i], &As[(wm*32 + i*16)*LDA_E + kk], LDA_E);
            #pragma unroll
            for (int j = 0; j < NF; j++)
                wmma::load_matrix_sync(fb[j], &Bs[kk*LDB_E + wn*(16*NF) + j*16], LDB_E);
            #pragma unroll
            for (int i = 0; i < 2; i++)
                #pragma unroll
                for (int j = 0; j < NF; j++)
                    wmma::mma_sync(acc[i][j], fa[i], fb[j], acc[i][j]);
        }
    }
    __syncthreads();

    float* Cs = (float*)smc;
    #pragma unroll
    for (int i = 0; i < 2; i++)
        #pragma unroll
        for (int j = 0; j < NF; j++)
            wmma::store_matrix_sync(&Cs[(wm*32 + i*16)*LDC_ + wn*(16*NF) + j*16],
                                    acc[i][j], LDC_, wmma::mem_row_major);
    __syncthreads();

    int er   = tid >> 1;
    int ecol = (tid & 1) * (BN_/2);
    #pragma unroll
    for (int i = 0; i < BN_/8; i++){
        int cc = ecol + i*4;
        float4 v = *(const float4*)&Cs[er*LDC_ + cc];
        size_t gr = czoff + (size_t)(row0 + er)*ldc + col0 + cc;
        v.x += bias[col0+cc+0]; v.y += bias[col0+cc+1];
        v.z += bias[col0+cc+2]; v.w += bias[col0+cc+3];
        if (flags & FLAG_SIG){
            v.x = sigf(v.x); v.y = sigf(v.y); v.z = sigf(v.z); v.w = sigf(v.w);
        }
        if (HOUT){
            __half2 p0 = __floats2half2_rn(v.x, v.y);
            __half2 p1 = __floats2half2_rn(v.z, v.w);
            *(uint2*)((half_t*)Cv + gr) = make_uint2(*(uint32_t*)&p0, *(uint32_t*)&p1);
        } else {
            *(float4*)((float*)Cv + gr) = v;
        }
    }
}

#define H_SMEM_128 (3*(BM*LDA_E*2 + BK64*(128+8)*2))   // 107520
#define H_SMEM_64  (3*(BM*LDA_E*2 + BK64*(64+8)*2))    // 82944

// -------------------- elementwise / reductions --------------------
// standalone gate (layer 0 only)
__global__ void gate_k(const float* __restrict__ h, const float* __restrict__ deg,
                       const float* __restrict__ Wd, const float* __restrict__ bd,
                       half_t* __restrict__ hgh){
    int n = blockIdx.x, t = threadIdx.x;
    float d = deg[n];
    float4 hv = ((const float4*)(h + (size_t)n*HH))[t];
    float4 wv = ((const float4*)Wd)[t];
    float4 bv = ((const float4*)bd)[t];
    float4 o;
    o.x = hv.x * sigf(d*wv.x + bv.x);
    o.y = hv.y * sigf(d*wv.y + bv.y);
    o.z = hv.z * sigf(d*wv.z + bv.z);
    o.w = hv.w * sigf(d*wv.w + bv.w);
    __half2 p0 = __floats2half2_rn(o.x, o.y);
    __half2 p1 = __floats2half2_rn(o.z, o.w);
    ((uint2*)(hgh + (size_t)n*HH))[t] = make_uint2(*(uint32_t*)&p0, *(uint32_t*)&p1);
}

// sparse masked attention: warp/node, smem neighbor list, 4-way batched.
__global__ void __launch_bounds__(256)
attn_k(const half_t* __restrict__ qk, const half_t* __restrict__ hg,
       const unsigned* __restrict__ adj, const int* __restrict__ starts,
       const int* __restrict__ batch, half_t* __restrict__ outh){
    __shared__ uint16_t nbr[8][NMAX];
    int gwarp = (blockIdx.x*blockDim.x + threadIdx.x) >> 5;
    int lane  = threadIdx.x & 31;
    int wslot = threadIdx.x >> 5;
    if (gwarp >= NN) return;
    int n = gwarp;
    int b = batch[n];
    int start = starts[b];
    int p = n - start;
    const unsigned* row = adj + ((size_t)b*NMAX + p)*ADJW;

    unsigned word = (lane < ADJW) ? row[lane] : 0u;
    int cnt = __popc(word);
    int pre = cnt;
    #pragma unroll
    for (int o = 1; o < 32; o <<= 1){
        int t = __shfl_up_sync(0xffffffffu, pre, o);
        if (lane >= o) pre += t;
    }
    int deg = __shfl_sync(0xffffffffu, pre, 31);
    int wr  = pre - cnt;
    uint16_t* lst = nbr[wslot];
    while (word){
        int t = __ffs((int)word) - 1; word &= word - 1;
        lst[wr++] = (uint16_t)(lane*32 + t);
    }
    __syncwarp();

    const uint4* qn4 = (const uint4*)(qk + (size_t)n*HH);
    float qnf[16];
    #pragma unroll
    for (int c = 0; c < 2; c++){
        uint4 u = qn4[lane + c*32];
        #pragma unroll
        for (int w = 0; w < 4; w++){
            float2 f = __half22float2(((const __half2*)&u)[w]);
            qnf[c*8 + 2*w]     = f.x;
            qnf[c*8 + 2*w + 1] = f.y;
        }
    }
    float accf[16] = {};
    float rowsum = 0.f;
    const float inv_sqrt_h = 0.044194173824159216f;

    for (int i = 0; i < deg; i += 4){
        int pp[4]; bool hv[4];
        #pragma unroll
        for (int q = 0; q < 4; q++){
            hv[q] = (i + q < deg);
            pp[q] = lst[hv[q] ? (i+q) : i];
        }
        float sc[4] = {0.f, 0.f, 0.f, 0.f};
        const uint4* qp[4];
        #pragma unroll
        for (int q = 0; q < 4; q++)
            qp[q] = (const uint4*)(qk + (size_t)(start+pp[q])*HH);
        #pragma unroll
        for (int c = 0; c < 2; c++){
            uint4 uu[4];
            #pragma unroll
            for (int q = 0; q < 4; q++) uu[q] = qp[q][lane + c*32];
            #pragma unroll
            for (int w = 0; w < 4; w++){
                float a0 = qnf[c*8+2*w], a1 = qnf[c*8+2*w+1];
                #pragma unroll
                for (int q = 0; q < 4; q++){
                    float2 f = __half22float2(((const __half2*)&uu[q])[w]);
                    sc[q] += a0*f.x + a1*f.y;
                }
            }
        }
        #pragma unroll
        for (int o = 16; o; o >>= 1)
            #pragma unroll
            for (int q = 0; q < 4; q++)
                sc[q] += __shfl_xor_sync(0xffffffffu, sc[q], o);
        #pragma unroll
        for (int q = 0; q < 4; q++){
            sc[q] = hv[q] ? sc[q]*inv_sqrt_h : 0.f;
            rowsum += sc[q];
        }
        const uint4* hp[4];
        #pragma unroll
        for (int q = 0; q < 4; q++)
            hp[q] = (const uint4*)(hg + (size_t)(start+pp[q])*HH);
        #pragma unroll
        for (int c = 0; c < 2; c++){
            uint4 uu[4];
            #pragma unroll
            for (int q = 0; q < 4; q++) uu[q] = hp[q][lane + c*32];
            #pragma unroll
            for (int w = 0; w < 4; w++){
                #pragma unroll
                for (int q = 0; q < 4; q++){
                    float2 f = __half22float2(((const __half2*)&uu[q])[w]);
                    accf[c*8+2*w]     += sc[q]*f.x;
                    accf[c*8+2*w + 1] += sc[q]*f.y;
                }
            }
        }
    }
    float inv = 1.f/(rowsum + 1e-6f);
    uint4* o4 = (uint4*)(outh + (size_t)n*HH);
    #pragma unroll
    for (int c = 0; c < 2; c++){
        uint4 u;
        #pragma unroll
        for (int w = 0; w < 4; w++){
            __half2 pk = __floats2half2_rn(accf[c*8+2*w]*inv, accf[c*8+2*w+1]*inv);
            ((uint32_t*)&u)[w] = *(uint32_t*)&pk;
        }
        o4[lane + c*32] = u;
    }
}

// fused: h = relu(l2norm(ob)); hnh = fp16(LN(h)*g+b)
__global__ void l2ln_k(const float* __restrict__ x, float* __restrict__ h,
                       half_t* __restrict__ hnh, const float* __restrict__ g,
                       const float* __restrict__ b){
    int n = blockIdx.x, t = threadIdx.x;
    float4 v = ((const float4*)(x + (size_t)n*HH))[t];
    float ss = v.x*v.x + v.y*v.y + v.z*v.z + v.w*v.w;
    #pragma unroll
    for (int o = 16; o; o >>= 1) ss += __shfl_xor_sync(0xffffffffu, ss, o);
    __shared__ float sh[4], sh2[4], red[3];
    int w = t >> 5, l = t & 31;
    if (l == 0) sh[w] = ss;
    __syncthreads();
    if (t == 0) red[0] = 1.f / fmaxf(sqrtf(sh[0]+sh[1]+sh[2]+sh[3]), 1e-12f);
    __syncthreads();
    float iv = red[0];
    float4 hv;
    hv.x = fmaxf(v.x*iv, 0.f); hv.y = fmaxf(v.y*iv, 0.f);
    hv.z = fmaxf(v.z*iv, 0.f); hv.w = fmaxf(v.w*iv, 0.f);
    ((float4*)(h + (size_t)n*HH))[t] = hv;
    float s  = hv.x + hv.y + hv.z + hv.w;
    float s2 = hv.x*hv.x + hv.y*hv.y + hv.z*hv.z + hv.w*hv.w;
    #pragma unroll
    for (int o = 16; o; o >>= 1){
        s  += __shfl_xor_sync(0xffffffffu, s,  o);
        s2 += __shfl_xor_sync(0xffffffffu, s2, o);
    }
    if (l == 0){ sh[w] = s; sh2[w] = s2; }
    __syncthreads();
    if (t == 0){
        float ts = sh[0]+sh[1]+sh[2]+sh[3], ts2 = sh2[0]+sh2[1]+sh2[2]+sh2[3];
        float mean = ts / HH;
        red[1] = mean; red[2] = rsqrtf(ts2/HH - mean*mean + 1e-5f);
    }
    __syncthreads();
    float mean = red[1], rstd = red[2];
    float4 gv = ((const float4*)g)[t];
    float4 bv = ((const float4*)b)[t];
    float4 o;
    o.x = (hv.x-mean)*rstd*gv.x + bv.x;
    o.y = (hv.y-mean)*rstd*gv.y + bv.y;
    o.z = (hv.z-mean)*rstd*gv.z + bv.z;
    o.w = (hv.w-mean)*rstd*gv.w + bv.w;
    __half2 p0 = __floats2half2_rn(o.x, o.y);
    __half2 p1 = __floats2half2_rn(o.z, o.w);
    ((uint2*)(hnh + (size_t)n*HH))[t] = make_uint2(*(uint32_t*)&p0, *(uint32_t*)&p1);
}

// LN(256)+relu over up rows, fp16 in/out, half2-vectorized (64 thr x 4 halves)
__global__ void ln_up_k(half_t* __restrict__ y,
                        const float* __restrict__ g, const float* __restrict__ b){
    int row = blockIdx.x, t = threadIdx.x;   // 64 threads
    uint2* yr = (uint2*)(y + (size_t)row*HFG);
    uint2 u = yr[t];
    float2 f0 = __half22float2(((const __half2*)&u)[0]);
    float2 f1 = __half22float2(((const __half2*)&u)[1]);
    float s = f0.x + f0.y + f1.x + f1.y;
    float s2 = f0.x*f0.x + f0.y*f0.y + f1.x*f1.x + f1.y*f1.y;
    #pragma unroll
    for (int o = 16; o; o >>= 1){
        s  += __shfl_xor_sync(0xffffffffu, s,  o);
        s2 += __shfl_xor_sync(0xffffffffu, s2, o);
    }
    __shared__ float sh[2][2], mb[2];
    int w = t >> 5, l = t & 31;
    if (l == 0){ sh[0][w] = s; sh[1][w] = s2; }
    __syncthreads();
    if (t == 0){
        float ts = sh[0][0]+sh[0][1], ts2 = sh[1][0]+sh[1][1];
        float mean = ts / HFG;
        mb[0] = mean; mb[1] = rsqrtf(ts2/HFG - mean*mean + 1e-5f);
    }
    __syncthreads();
    float mean = mb[0], rstd = mb[1];
    int c = t*4;
    float o0 = fmaxf((f0.x-mean)*rstd*g[c+0] + b[c+0], 0.f);
    float o1 = fmaxf((f0.y-mean)*rstd*g[c+1] + b[c+1], 0.f);
    float o2 = fmaxf((f1.x-mean)*rstd*g[c+2] + b[c+2], 0.f);
    float o3 = fmaxf((f1.y-mean)*rstd*g[c+3] + b[c+3], 0.f);
    __half2 p0 = __floats2half2_rn(o0, o1);
    __half2 p1 = __floats2half2_rn(o2, o3);
    yr[t] = make_uint2(*(uint32_t*)&p0, *(uint32_t*)&p1);
}

// fused: LN(64) + LayerScale residual into h; optionally emits next-layer gate
template<bool GATE>
__global__ void ln_res_k(const half_t* __restrict__ dnv, float* __restrict__ h,
                         const float* __restrict__ g, const float* __restrict__ b,
                         const float* __restrict__ gamma,
                         const float* __restrict__ degv,
                         const float* __restrict__ Wd, const float* __restrict__ bd,
                         half_t* __restrict__ hgh){
    int row = blockIdx.x;            // node n = row >> 3, group = row & 7
    int t   = threadIdx.x;           // 64
    float u = __half2float(dnv[(size_t)row*HG + t]);
    float s = u, s2 = u*u;
    #pragma unroll
    for (int o = 16; o; o >>= 1){
        s  += __shfl_xor_sync(0xffffffffu, s,  o);
        s2 += __shfl_xor_sync(0xffffffffu, s2, o);
    }
    __shared__ float sa[2], sbv[2];
    int w = t >> 5, l = t & 31;
    if (l == 0){ sa[w] = s; sbv[w] = s2; }
    __syncthreads();
    float ts = sa[0]+sa[1], ts2 = sbv[0]+sbv[1];
    float mean = ts / HG;
    float rstd = rsqrtf(ts2/HG - mean*mean + 1e-5f);
    float o = (u - mean)*rstd*g[t] + b[t];
    int gi = (row & (GG-1))*HG + t;   // channel index in [0,512)
    size_t idx = (size_t)row*HG + t;
    float hn = h[idx] + gamma[gi]*o;
    h[idx] = hn;
    if (GATE){
        float d = degv[row >> 3];
        float gate = sigf(d*Wd[gi] + bd[gi]);
        hgh[idx] = __float2half_rn(hn * gate);
    }
}

// parallel pool: node-parallel partial sums + atomicAdd (out pre-zeroed)
__global__ void pool_k(const float* __restrict__ h, const int* __restrict__ batch,
                       float* __restrict__ out){
    int n = blockIdx.x;              // node
    int f = threadIdx.x;             // 128 threads, float4 each
    int b = batch[n];
    float4 v = ((const float4*)(h + (size_t)n*HH))[f];
    float* ob = out + (size_t)b*HH + f*4;
    atomicAdd(ob+0, v.x); atomicAdd(ob+1, v.y);
    atomicAdd(ob+2, v.z); atomicAdd(ob+3, v.w);
}

// -------------------- launcher --------------------
extern "C" void kernel_launch(void* const* d_in, const int* in_sizes, int n_in,
                              void* d_out, int out_size){
    const float* x     = (const float*)d_in[0];
    const int*   ei    = (const int*)d_in[1];
    const int*   batch = (const int*)d_in[2];
    const float* W_in = (const float*)d_in[3];
    const float* b_in = (const float*)d_in[4];
    const float* Wqk  = (const float*)d_in[5];
    const float* bqk  = (const float*)d_in[6];
    const float* Wd   = (const float*)d_in[7];
    const float* bd   = (const float*)d_in[8];
    const float* Wl   = (const float*)d_in[9];
    const float* bl   = (const float*)d_in[10];
    const float* Wr   = (const float*)d_in[11];
    const float* gamma= (const float*)d_in[12];
    const float* ln_g = (const float*)d_in[13];
    const float* ln_b = (const float*)d_in[14];
    const float* up_w = (const float*)d_in[15];
    const float* up_b = (const float*)d_in[16];
    const float* up_lg= (const float*)d_in[17];
    const float* up_lb= (const float*)d_in[18];
    const float* dn_w = (const float*)d_in[19];
    const float* dn_b = (const float*)d_in[20];
    const float* dn_lg= (const float*)d_in[21];
    const float* dn_lb= (const float*)d_in[22];
    float* out = (float*)d_out;

    float *h, *ob, *deg;
    half_t *xh, *hgh, *qkh, *atth, *hnh, *uph, *dnh, *Winh, *Wqkh, *Wlh, *Wrh, *upwh, *dnwh;
    int *starts, *pos; unsigned* adj;
    cudaGetSymbolAddress((void**)&h,   g_h);
    cudaGetSymbolAddress((void**)&ob,  g_out);
    cudaGetSymbolAddress((void**)&deg, g_deg);
    cudaGetSymbolAddress((void**)&starts, g_starts);
    cudaGetSymbolAddress((void**)&pos,    g_pos);
    cudaGetSymbolAddress((void**)&adj,    g_adj);
    cudaGetSymbolAddress((void**)&xh,   g_xh);
    cudaGetSymbolAddress((void**)&hgh,  g_hgh);
    cudaGetSymbolAddress((void**)&qkh,  g_qkh);
    cudaGetSymbolAddress((void**)&atth, g_atth);
    cudaGetSymbolAddress((void**)&hnh,  g_hnh);
    cudaGetSymbolAddress((void**)&uph,  g_uph);
    cudaGetSymbolAddress((void**)&dnh,  g_dnh);
    cudaGetSymbolAddress((void**)&Winh, g_Winh);
    cudaGetSymbolAddress((void**)&Wqkh, g_Wqkh);
    cudaGetSymbolAddress((void**)&Wlh,  g_Wlh);
    cudaGetSymbolAddress((void**)&Wrh,  g_Wrh);
    cudaGetSymbolAddress((void**)&upwh, g_upwh);
    cudaGetSymbolAddress((void**)&dnwh, g_dnwh);

    cudaFuncSetAttribute((const void*)gemm_h<128,false,false>,
                         cudaFuncAttributeMaxDynamicSharedMemorySize, H_SMEM_128);
    cudaFuncSetAttribute((const void*)gemm_h<128,false,true>,
                         cudaFuncAttributeMaxDynamicSharedMemorySize, H_SMEM_128);
    cudaFuncSetAttribute((const void*)gemm_h<128,true,false>,
                         cudaFuncAttributeMaxDynamicSharedMemorySize, H_SMEM_128);
    cudaFuncSetAttribute((const void*)gemm_h<64,false,true>,
                         cudaFuncAttributeMaxDynamicSharedMemorySize, H_SMEM_64);

    convert_k<<<NN*FF/1024, 256>>>(x, xh, NN*FF);
    convert_k<<<FF*HH/1024, 256>>>(W_in, Winh, FF*HH);
    clear_adj_k<<<(int)((ADJTOT + 255)/256), 256>>>(adj, ob == nullptr ? nullptr : out);

    // h = x @ W_in + b_in   (K=128)
    gemm_h<128,false,false><<<dim3(HH/128, NN/BM, 1), 256, H_SMEM_128>>>(
        xh, FF, 0, Winh, HH, 0, nullptr, nullptr, h, HH, 0, b_in, 0, FF, 0);

    starts_k  <<<NN/256, 256>>>(batch, starts);
    pos_self_k<<<NN/256, 256>>>(batch, starts, pos, adj);
    edge_k<<<EE/256, 256>>>(ei, batch, pos, adj);
    deg_k <<<NN/256, 256>>>(batch, pos, adj, deg);

    convert_k<<<LL*HH*HH/1024, 256>>>(Wqk, Wqkh, LL*HH*HH);
    convert_k<<<LL*HH*HH/1024, 256>>>(Wl, Wlh, LL*HH*HH);
    convert_k<<<LL*HH*HH/1024, 256>>>(Wr, Wrh, LL*HH*HH);
    convert_k<<<LL*GG*HG*HFG/1024, 256>>>(up_w, upwh, LL*GG*HG*HFG);
    convert_k<<<LL*GG*HFG*HG/1024, 256>>>(dn_w, dnwh, LL*GG*HFG*HG);

    // layer-0 gate (later layers fused into ln_res)
    gate_k<<<NN, 128>>>(h, deg, Wd, bd, hgh);

    for (int l = 0; l < LL; l++){
        // qk = sigmoid(hg@Wqk + bqk)  -> fp16 output
        gemm_h<128,false,true><<<dim3(HH/128, NN/BM, 1), 256, H_SMEM_128>>>(
            hgh, HH, 0, Wqkh + (size_t)l*HH*HH, HH, 0, nullptr, nullptr,
            qkh, HH, 0, bqk + l*HH, 0, HH, FLAG_SIG);
        attn_k<<<NN/8, 256>>>(qkh, hgh, adj, starts, batch, atth);
        // ob = att@Wl + hg@Wr + bl  (fp16 dual, fp32 out)
        gemm_h<128,true,false><<<dim3(HH/128, NN/BM, 1), 256, H_SMEM_128>>>(
            atth, HH, 0, Wlh + (size_t)l*HH*HH, HH, 0,
            hgh, Wrh + (size_t)l*HH*HH,
            ob, HH, 0, bl + l*HH, 0, HH, 0);
        l2ln_k<<<NN, 128>>>(ob, h, hnh, ln_g + l*HH, ln_b + l*HH);
        // grouped up (fp16): [N,64]@[64,256]  K=64 -> fp16 out
        gemm_h<128,false,true><<<dim3(HFG/128, NN/BM, GG), 256, H_SMEM_128>>>(
            hnh, HH, HG, upwh + (size_t)l*GG*HG*HFG, HFG, (long long)HG*HFG,
            nullptr, nullptr, uph, HFF, HFG, up_b + (size_t)l*GG*HFG, HFG, 64, 0);
        ln_up_k<<<NN*GG, 64>>>(uph, up_lg + l*HFG, up_lb + l*HFG);
        // grouped down (fp16): [N,256]@[256,64]  K=256 -> fp16 out
        gemm_h<64,false,true><<<dim3(1, NN/BM, GG), 256, H_SMEM_64>>>(
            uph, HFF, HFG, dnwh + (size_t)l*GG*HFG*HG, HG, (long long)HFG*HG,
            nullptr, nullptr, dnh, HH, HG, dn_b + (size_t)l*GG*HG, HG, 256, 0);
        // LN(64) + residual; layers 0,1 also emit next layer's gated hgh
        if (l + 1 < LL){
            ln_res_k<true><<<NN*GG, 64>>>(dnh, h, dn_lg + l*HG, dn_lb + l*HG,
                                          gamma + l*HH, deg,
                                          Wd + (l+1)*HH, bd + (l+1)*HH, hgh);
        } else {
            ln_res_k<false><<<NN*GG, 64>>>(dnh, h, dn_lg + l*HG, dn_lb + l*HG,
                                           gamma + l*HH, nullptr, nullptr, nullptr, nullptr);
        }
    }

    pool_k<<<NN, 128>>>(h, batch, out);
}

// round 17
// speedup vs baseline: 1.0377x; 1.0377x over previous
#include <cuda_runtime.h>
#include <cuda_bf16.h>
#include <cuda_fp16.h>
#include <mma.h>
#include <cstdint>
#include <math.h>

using namespace nvcuda;

// Problem constants (fixed instance)
#define NN    8192
#define BB    32
#define NMAX  512
#define FF    128
#define HH    512
#define LL    3
#define GG    8
#define HFF   2048
#define EE    131072
#define HG    (HH/GG)    // 64
#define HFG   (HFF/GG)   // 256
#define ADJW  16
#define ADJTOT ((size_t)BB*NMAX*ADJW)

#define FLAG_SIG 2

// fp16 GEMM tiling: 128xBN block tile, BK=64, 3-stage cp.async
#define BM    128
#define BK64  64
#define LDA_E 72     // half elems/row (144B) -> ldmatrix conflict-free

typedef __half half_t;

// -------------------- scratch (device globals; no allocs) --------------------
__device__ __align__(16) float g_h  [NN*HH];
__device__ __align__(16) float g_out[NN*HH];
__device__ float    g_deg[NN];
__device__ int      g_starts[BB+1];
__device__ int      g_pos[NN];
__device__ unsigned g_adj[ADJTOT];
// fp16 operands
__device__ __align__(16) half_t g_xh  [NN*FF];
__device__ __align__(16) half_t g_hgh [NN*HH];
__device__ __align__(16) half_t g_qkh [NN*HH];
__device__ __align__(16) half_t g_atth[NN*HH];
__device__ __align__(16) half_t g_hnh [NN*HH];
__device__ __align__(16) half_t g_uph [NN*HFF];
__device__ __align__(16) half_t g_dnh [NN*HH];
__device__ __align__(16) half_t g_Winh[FF*HH];
__device__ __align__(16) half_t g_Wqkh[LL*HH*HH];
__device__ __align__(16) half_t g_Wlh [LL*HH*HH];
__device__ __align__(16) half_t g_Wrh [LL*HH*HH];
__device__ __align__(16) half_t g_upwh[LL*GG*HG*HFG];
__device__ __align__(16) half_t g_dnwh[LL*GG*HFG*HG];

__device__ __forceinline__ float sigf(float x){ return 1.f/(1.f+__expf(-x)); }

__device__ __forceinline__ void cpa16(uint32_t s, const void* g){
    asm volatile("cp.async.cg.shared.global [%0], [%1], 16;" :: "r"(s), "l"(g));
}
__device__ __forceinline__ void cpa_commit(){ asm volatile("cp.async.commit_group;"); }
template<int N> __device__ __forceinline__ void cpa_wait(){
    asm volatile("cp.async.wait_group %0;" :: "n"(N));
}
__device__ __forceinline__ uint32_t smem_u32(const void* p){
    uint32_t a;
    asm("{ .reg .u64 t; cvta.to.shared.u64 t, %1; cvt.u32.u64 %0, t; }" : "=r"(a) : "l"(p));
    return a;
}

// -------------------- fp32 -> fp16 (rn) bulk convert --------------------
__global__ void convert_k(const float* __restrict__ src, half_t* __restrict__ dst, int n){
    int i = (blockIdx.x*blockDim.x + threadIdx.x) * 4;
    if (i >= n) return;
    float4 v = *(const float4*)(src + i);
    __half2 p0 = __floats2half2_rn(v.x, v.y);
    __half2 p1 = __floats2half2_rn(v.z, v.w);
    *(uint2*)(dst + i) = make_uint2(*(uint32_t*)&p0, *(uint32_t*)&p1);
}

// -------------------- graph structure --------------------
__global__ void clear_adj_k(unsigned* __restrict__ adj){
    size_t i = (size_t)blockIdx.x*blockDim.x + threadIdx.x;
    if (i < ADJTOT) adj[i] = 0u;
}
__global__ void starts_k(const int* __restrict__ batch, int* __restrict__ starts){
    int n = blockIdx.x*blockDim.x + threadIdx.x;
    if (n >= NN) return;
    if (n == 0){ starts[batch[0]] = 0; starts[BB] = NN; }
    else if (batch[n] != batch[n-1]) starts[batch[n]] = n;
}
__global__ void pos_self_k(const int* __restrict__ batch, const int* __restrict__ starts,
                           int* __restrict__ pos, unsigned* __restrict__ adj){
    int n = blockIdx.x*blockDim.x + threadIdx.x;
    if (n >= NN) return;
    int b = batch[n];
    int p = n - starts[b];
    pos[n] = p;
    atomicOr(&adj[((size_t)b*NMAX + p)*ADJW + (p>>5)], 1u << (p&31));
}
__global__ void edge_k(const int* __restrict__ ei, const int* __restrict__ batch,
                       const int* __restrict__ pos, unsigned* __restrict__ adj){
    int e = blockIdx.x*blockDim.x + threadIdx.x;
    if (e >= EE) return;
    int s = ei[e];
    int d = ei[EE + e];
    int b = batch[s];
    atomicOr(&adj[((size_t)b*NMAX + pos[s])*ADJW + (pos[d]>>5)], 1u << (pos[d]&31));
}
__global__ void deg_k(const int* __restrict__ batch, const int* __restrict__ pos,
                      const unsigned* __restrict__ adj, float* __restrict__ deg){
    int n = blockIdx.x*blockDim.x + threadIdx.x;
    if (n >= NN) return;
    const unsigned* row = adj + ((size_t)batch[n]*NMAX + pos[n])*ADJW;
    int c = 0;
    #pragma unroll
    for (int w = 0; w < ADJW; w++) c += __popc(row[w]);
    deg[n] = (float)c;
}

// -------------------- fp16 tensor-core GEMM (unified) ------------------------
template<int BN_, bool DUAL, bool HOUT>
__global__ void __launch_bounds__(256, 2)
gemm_h(const half_t* __restrict__ A, int lda, long long sAz,
       const half_t* __restrict__ W, int ldw, long long sWz,
       const half_t* __restrict__ A2, const half_t* __restrict__ W2,
       void* __restrict__ Cv, int ldc, long long sCz,
       const float* __restrict__ bias, long long sBz,
       int K, int flags)
{
    constexpr int LDB_E = BN_ + 8;
    constexpr int LDC_  = BN_ + 4;
    constexpr int ASZB  = BM * LDA_E * 2;
    constexpr int BSZB  = BK64 * LDB_E * 2;
    constexpr int STGB  = ASZB + BSZB;
    constexpr int NF    = BN_ / 32;
    constexpr int BROW8 = BN_ / 8;
    constexpr int BCH   = (BK64 * BROW8) / 256;

    A += (size_t)blockIdx.z * sAz;
    W += (size_t)blockIdx.z * sWz;
    size_t czoff = (size_t)blockIdx.z * sCz;
    bias += (size_t)blockIdx.z * sBz;

    extern __shared__ __align__(16) char smc[];

    int tid  = threadIdx.x;
    int warp = tid >> 5;
    int wm   = warp >> 1;
    int wn   = warp & 1;
    int row0 = blockIdx.y * BM;
    int col0 = blockIdx.x * BN_;

    wmma::fragment<wmma::accumulator, 16, 16, 16, float> acc[2][NF];
    #pragma unroll
    for (int i = 0; i < 2; i++)
        #pragma unroll
        for (int j = 0; j < NF; j++)
            wmma::fill_fragment(acc[i][j], 0.0f);

    const int T  = K / BK64;
    const int TT = DUAL ? 2*T : T;

    auto prefetch = [&](int j){
        const half_t* Ap = (DUAL && j >= T) ? A2 : A;
        const half_t* Wp = (DUAL && j >= T) ? W2 : W;
        int k0 = (DUAL ? (j % T) : j) * BK64;
        uint32_t a0 = smem_u32(smc + (j % 3)*STGB);
        uint32_t b0 = a0 + ASZB;
        #pragma unroll
        for (int i = 0; i < 4; i++){
            int f = tid + i*256, r = f >> 3, c = f & 7;
            cpa16(a0 + r*(LDA_E*2) + c*16, Ap + (size_t)(row0+r)*lda + k0 + c*8);
        }
        #pragma unroll
        for (int i = 0; i < BCH; i++){
            int f = tid + i*256, r = f / BROW8, c = f % BROW8;
            cpa16(b0 + r*(LDB_E*2) + c*16, Wp + (size_t)(k0+r)*ldw + col0 + c*8);
        }
        cpa_commit();
    };

    prefetch(0);
    if (TT > 1) prefetch(1);

    for (int it = 0; it < TT; it++){
        if (it + 1 < TT) cpa_wait<1>(); else cpa_wait<0>();
        __syncthreads();
        if (it + 2 < TT) prefetch(it + 2);

        half_t* As = (half_t*)(smc + (it % 3)*STGB);
        half_t* Bs = (half_t*)(smc + (it % 3)*STGB + ASZB);
        #pragma unroll
        for (int kk = 0; kk < BK64; kk += 16){
            wmma::fragment<wmma::matrix_a, 16, 16, 16, half_t, wmma::row_major> fa[2];
            wmma::fragment<wmma::matrix_b, 16, 16, 16, half_t, wmma::row_major> fb[NF];
            #pragma unroll
            for (int i = 0; i < 2; i++)
                wmma::load_matrix_sync(fa[i], &As[(wm*32 + i*16)*LDA_E + kk], LDA_E);
            #pragma unroll
            for (int j = 0; j < NF; j++)
                wmma::load_matrix_sync(fb[j], &Bs[kk*LDB_E + wn*(16*NF) + j*16], LDB_E);
            #pragma unroll
            for (int i = 0; i < 2; i++)
                #pragma unroll
                for (int j = 0; j < NF; j++)
                    wmma::mma_sync(acc[i][j], fa[i], fb[j], acc[i][j]);
        }
    }
    __syncthreads();

    float* Cs = (float*)smc;
    #pragma unroll
    for (int i = 0; i < 2; i++)
        #pragma unroll
        for (int j = 0; j < NF; j++)
            wmma::store_matrix_sync(&Cs[(wm*32 + i*16)*LDC_ + wn*(16*NF) + j*16],
                                    acc[i][j], LDC_, wmma::mem_row_major);
    __syncthreads();

    int er   = tid >> 1;
    int ecol = (tid & 1) * (BN_/2);
    #pragma unroll
    for (int i = 0; i < BN_/8; i++){
        int cc = ecol + i*4;
        float4 v = *(const float4*)&Cs[er*LDC_ + cc];
        size_t gr = czoff + (size_t)(row0 + er)*ldc + col0 + cc;
        v.x += bias[col0+cc+0]; v.y += bias[col0+cc+1];
        v.z += bias[col0+cc+2]; v.w += bias[col0+cc+3];
        if (flags & FLAG_SIG){
            v.x = sigf(v.x); v.y = sigf(v.y); v.z = sigf(v.z); v.w = sigf(v.w);
        }
        if (HOUT){
            __half2 p0 = __floats2half2_rn(v.x, v.y);
            __half2 p1 = __floats2half2_rn(v.z, v.w);
            *(uint2*)((half_t*)Cv + gr) = make_uint2(*(uint32_t*)&p0, *(uint32_t*)&p1);
        } else {
            *(float4*)((float*)Cv + gr) = v;
        }
    }
}

#define H_SMEM_128 (3*(BM*LDA_E*2 + BK64*(128+8)*2))   // 107520
#define H_SMEM_64  (3*(BM*LDA_E*2 + BK64*(64+8)*2))    // 82944

// -------------------- elementwise / reductions --------------------
// standalone gate (layer 0 only)
__global__ void gate_k(const float* __restrict__ h, const float* __restrict__ deg,
                       const float* __restrict__ Wd, const float* __restrict__ bd,
                       half_t* __restrict__ hgh){
    int n = blockIdx.x, t = threadIdx.x;
    float d = deg[n];
    float4 hv = ((const float4*)(h + (size_t)n*HH))[t];
    float4 wv = ((const float4*)Wd)[t];
    float4 bv = ((const float4*)bd)[t];
    float4 o;
    o.x = hv.x * sigf(d*wv.x + bv.x);
    o.y = hv.y * sigf(d*wv.y + bv.y);
    o.z = hv.z * sigf(d*wv.z + bv.z);
    o.w = hv.w * sigf(d*wv.w + bv.w);
    __half2 p0 = __floats2half2_rn(o.x, o.y);
    __half2 p1 = __floats2half2_rn(o.z, o.w);
    ((uint2*)(hgh + (size_t)n*HH))[t] = make_uint2(*(uint32_t*)&p0, *(uint32_t*)&p1);
}

// sparse masked attention: warp/node, smem neighbor list, 2-way batched
// (round-14/15 validated config).  fp16 in, fp32 compute, fp16 out.
__global__ void __launch_bounds__(256)
attn_k(const half_t* __restrict__ qk, const half_t* __restrict__ hg,
       const unsigned* __restrict__ adj, const int* __restrict__ starts,
       const int* __restrict__ batch, half_t* __restrict__ outh){
    __shared__ uint16_t nbr[8][NMAX];
    int gwarp = (blockIdx.x*blockDim.x + threadIdx.x) >> 5;
    int lane  = threadIdx.x & 31;
    int wslot = threadIdx.x >> 5;
    if (gwarp >= NN) return;
    int n = gwarp;
    int b = batch[n];
    int start = starts[b];
    int p = n - start;
    const unsigned* row = adj + ((size_t)b*NMAX + p)*ADJW;

    unsigned word = (lane < ADJW) ? row[lane] : 0u;
    int cnt = __popc(word);
    int pre = cnt;
    #pragma unroll
    for (int o = 1; o < 32; o <<= 1){
        int t = __shfl_up_sync(0xffffffffu, pre, o);
        if (lane >= o) pre += t;
    }
    int deg = __shfl_sync(0xffffffffu, pre, 31);
    int wr  = pre - cnt;
    uint16_t* lst = nbr[wslot];
    while (word){
        int t = __ffs((int)word) - 1; word &= word - 1;
        lst[wr++] = (uint16_t)(lane*32 + t);
    }
    __syncwarp();

    const uint4* qn4 = (const uint4*)(qk + (size_t)n*HH);
    float qnf[16];
    #pragma unroll
    for (int c = 0; c < 2; c++){
        uint4 u = qn4[lane + c*32];
        #pragma unroll
        for (int w = 0; w < 4; w++){
            float2 f = __half22float2(((const __half2*)&u)[w]);
            qnf[c*8 + 2*w]     = f.x;
            qnf[c*8 + 2*w + 1] = f.y;
        }
    }
    float accf[16] = {};
    float rowsum = 0.f;
    const float inv_sqrt_h = 0.044194173824159216f;

    for (int i = 0; i < deg; i += 2){
        int p0 = lst[i];
        int p1 = lst[(i+1 < deg) ? (i+1) : i];
        bool has1 = (i+1 < deg);
        const uint4* q0 = (const uint4*)(qk + (size_t)(start+p0)*HH);
        const uint4* q1 = (const uint4*)(qk + (size_t)(start+p1)*HH);
        float s0 = 0.f, s1 = 0.f;
        #pragma unroll
        for (int c = 0; c < 2; c++){
            uint4 a = q0[lane + c*32];
            uint4 e = q1[lane + c*32];
            #pragma unroll
            for (int w = 0; w < 4; w++){
                float2 fa = __half22float2(((const __half2*)&a)[w]);
                float2 fe = __half22float2(((const __half2*)&e)[w]);
                s0 += qnf[c*8+2*w]*fa.x + qnf[c*8+2*w+1]*fa.y;
                s1 += qnf[c*8+2*w]*fe.x + qnf[c*8+2*w+1]*fe.y;
            }
        }
        #pragma unroll
        for (int o = 16; o; o >>= 1){
            s0 += __shfl_xor_sync(0xffffffffu, s0, o);
            s1 += __shfl_xor_sync(0xffffffffu, s1, o);
        }
        s0 *= inv_sqrt_h;
        s1 = has1 ? s1*inv_sqrt_h : 0.f;
        rowsum += s0 + s1;
        const uint4* h0 = (const uint4*)(hg + (size_t)(start+p0)*HH);
        const uint4* h1 = (const uint4*)(hg + (size_t)(start+p1)*HH);
        #pragma unroll
        for (int c = 0; c < 2; c++){
            uint4 a = h0[lane + c*32];
            uint4 e = h1[lane + c*32];
            #pragma unroll
            for (int w = 0; w < 4; w++){
                float2 fa = __half22float2(((const __half2*)&a)[w]);
                float2 fe = __half22float2(((const __half2*)&e)[w]);
                accf[c*8+2*w]     += s0*fa.x + s1*fe.x;
                accf[c*8+2*w + 1] += s0*fa.y + s1*fe.y;
            }
        }
    }
    float inv = 1.f/(rowsum + 1e-6f);
    uint4* o4 = (uint4*)(outh + (size_t)n*HH);
    #pragma unroll
    for (int c = 0; c < 2; c++){
        uint4 u;
        #pragma unroll
        for (int w = 0; w < 4; w++){
            __half2 pk = __floats2half2_rn(accf[c*8+2*w]*inv, accf[c*8+2*w+1]*inv);
            ((uint32_t*)&u)[w] = *(uint32_t*)&pk;
        }
        o4[lane + c*32] = u;
    }
}

// fused: h = relu(l2norm(ob)); hnh = fp16(LN(h)*g+b)
__global__ void l2ln_k(const float* __restrict__ x, float* __restrict__ h,
                       half_t* __restrict__ hnh, const float* __restrict__ g,
                       const float* __restrict__ b){
    int n = blockIdx.x, t = threadIdx.x;
    float4 v = ((const float4*)(x + (size_t)n*HH))[t];
    float ss = v.x*v.x + v.y*v.y + v.z*v.z + v.w*v.w;
    #pragma unroll
    for (int o = 16; o; o >>= 1) ss += __shfl_xor_sync(0xffffffffu, ss, o);
    __shared__ float sh[4], sh2[4], red[3];
    int w = t >> 5, l = t & 31;
    if (l == 0) sh[w] = ss;
    __syncthreads();
    if (t == 0) red[0] = 1.f / fmaxf(sqrtf(sh[0]+sh[1]+sh[2]+sh[3]), 1e-12f);
    __syncthreads();
    float iv = red[0];
    float4 hv;
    hv.x = fmaxf(v.x*iv, 0.f); hv.y = fmaxf(v.y*iv, 0.f);
    hv.z = fmaxf(v.z*iv, 0.f); hv.w = fmaxf(v.w*iv, 0.f);
    ((float4*)(h + (size_t)n*HH))[t] = hv;
    float s  = hv.x + hv.y + hv.z + hv.w;
    float s2 = hv.x*hv.x + hv.y*hv.y + hv.z*hv.z + hv.w*hv.w;
    #pragma unroll
    for (int o = 16; o; o >>= 1){
        s  += __shfl_xor_sync(0xffffffffu, s,  o);
        s2 += __shfl_xor_sync(0xffffffffu, s2, o);
    }
    if (l == 0){ sh[w] = s; sh2[w] = s2; }
    __syncthreads();
    if (t == 0){
        float ts = sh[0]+sh[1]+sh[2]+sh[3], ts2 = sh2[0]+sh2[1]+sh2[2]+sh2[3];
        float mean = ts / HH;
        red[1] = mean; red[2] = rsqrtf(ts2/HH - mean*mean + 1e-5f);
    }
    __syncthreads();
    float mean = red[1], rstd = red[2];
    float4 gv = ((const float4*)g)[t];
    float4 bv = ((const float4*)b)[t];
    float4 o;
    o.x = (hv.x-mean)*rstd*gv.x + bv.x;
    o.y = (hv.y-mean)*rstd*gv.y + bv.y;
    o.z = (hv.z-mean)*rstd*gv.z + bv.z;
    o.w = (hv.w-mean)*rstd*gv.w + bv.w;
    __half2 p0 = __floats2half2_rn(o.x, o.y);
    __half2 p1 = __floats2half2_rn(o.z, o.w);
    ((uint2*)(hnh + (size_t)n*HH))[t] = make_uint2(*(uint32_t*)&p0, *(uint32_t*)&p1);
}

// LN(256)+relu over up rows, fp16 in/out, vectorized (64 thr x uint2)
__global__ void ln_up_k(half_t* __restrict__ y,
                        const float* __restrict__ g, const float* __restrict__ b){
    int row = blockIdx.x, t = threadIdx.x;   // 64 threads
    uint2* yr = (uint2*)(y + (size_t)row*HFG);
    uint2 u = yr[t];
    float2 f0 = __half22float2(((const __half2*)&u)[0]);
    float2 f1 = __half22float2(((const __half2*)&u)[1]);
    float s = f0.x + f0.y + f1.x + f1.y;
    float s2 = f0.x*f0.x + f0.y*f0.y + f1.x*f1.x + f1.y*f1.y;
    #pragma unroll
    for (int o = 16; o; o >>= 1){
        s  += __shfl_xor_sync(0xffffffffu, s,  o);
        s2 += __shfl_xor_sync(0xffffffffu, s2, o);
    }
    __shared__ float sh[2][2], mb[2];
    int w = t >> 5, l = t & 31;
    if (l == 0){ sh[0][w] = s; sh[1][w] = s2; }
    __syncthreads();
    if (t == 0){
        float ts = sh[0][0]+sh[0][1], ts2 = sh[1][0]+sh[1][1];
        float mean = ts / HFG;
        mb[0] = mean; mb[1] = rsqrtf(ts2/HFG - mean*mean + 1e-5f);
    }
    __syncthreads();
    float mean = mb[0], rstd = mb[1];
    int c = t*4;
    float o0 = fmaxf((f0.x-mean)*rstd*g[c+0] + b[c+0], 0.f);
    float o1 = fmaxf((f0.y-mean)*rstd*g[c+1] + b[c+1], 0.f);
    float o2 = fmaxf((f1.x-mean)*rstd*g[c+2] + b[c+2], 0.f);
    float o3 = fmaxf((f1.y-mean)*rstd*g[c+3] + b[c+3], 0.f);
    __half2 p0 = __floats2half2_rn(o0, o1);
    __half2 p1 = __floats2half2_rn(o2, o3);
    yr[t] = make_uint2(*(uint32_t*)&p0, *(uint32_t*)&p1);
}

// fused: LN(64) + LayerScale residual into h; optionally emits next-layer gate
template<bool GATE>
__global__ void ln_res_k(const half_t* __restrict__ dnv, float* __restrict__ h,
                         const float* __restrict__ g, const float* __restrict__ b,
                         const float* __restrict__ gamma,
                         const float* __restrict__ degv,
                         const float* __restrict__ Wd, const float* __restrict__ bd,
                         half_t* __restrict__ hgh){
    int row = blockIdx.x;            // node n = row >> 3, group = row & 7
    int t   = threadIdx.x;           // 64
    float u = __half2float(dnv[(size_t)row*HG + t]);
    float s = u, s2 = u*u;
    #pragma unroll
    for (int o = 16; o; o >>= 1){
        s  += __shfl_xor_sync(0xffffffffu, s,  o);
        s2 += __shfl_xor_sync(0xffffffffu, s2, o);
    }
    __shared__ float sa[2], sbv[2];
    int w = t >> 5, l = t & 31;
    if (l == 0){ sa[w] = s; sbv[w] = s2; }
    __syncthreads();
    float ts = sa[0]+sa[1], ts2 = sbv[0]+sbv[1];
    float mean = ts / HG;
    float rstd = rsqrtf(ts2/HG - mean*mean + 1e-5f);
    float o = (u - mean)*rstd*g[t] + b[t];
    int gi = (row & (GG-1))*HG + t;   // channel index in [0,512)
    size_t idx = (size_t)row*HG + t;
    float hn = h[idx] + gamma[gi]*o;
    h[idx] = hn;
    if (GATE){
        float d = degv[row >> 3];
        float gate = sigf(d*Wd[gi] + bd[gi]);
        hgh[idx] = __float2half_rn(hn * gate);
    }
}

// pool: per-(graph, feature-block) serial walk (round-15 validated)
__global__ void pool_k(const float* __restrict__ h, const int* __restrict__ starts,
                       float* __restrict__ out){
    int b = blockIdx.x;
    int f = blockIdx.y*128 + threadIdx.x;
    int s = starts[b], e = starts[b+1];
    float acc = 0.f;
    for (int n = s; n < e; n++) acc += h[(size_t)n*HH + f];
    out[(size_t)b*HH + f] = acc;
}

// -------------------- launcher --------------------
extern "C" void kernel_launch(void* const* d_in, const int* in_sizes, int n_in,
                              void* d_out, int out_size){
    const float* x     = (const float*)d_in[0];
    const int*   ei    = (const int*)d_in[1];
    const int*   batch = (const int*)d_in[2];
    const float* W_in = (const float*)d_in[3];
    const float* b_in = (const float*)d_in[4];
    const float* Wqk  = (const float*)d_in[5];
    const float* bqk  = (const float*)d_in[6];
    const float* Wd   = (const float*)d_in[7];
    const float* bd   = (const float*)d_in[8];
    const float* Wl   = (const float*)d_in[9];
    const float* bl   = (const float*)d_in[10];
    const float* Wr   = (const float*)d_in[11];
    const float* gamma= (const float*)d_in[12];
    const float* ln_g = (const float*)d_in[13];
    const float* ln_b = (const float*)d_in[14];
    const float* up_w = (const float*)d_in[15];
    const float* up_b = (const float*)d_in[16];
    const float* up_lg= (const float*)d_in[17];
    const float* up_lb= (const float*)d_in[18];
    const float* dn_w = (const float*)d_in[19];
    const float* dn_b = (const float*)d_in[20];
    const float* dn_lg= (const float*)d_in[21];
    const float* dn_lb= (const float*)d_in[22];
    float* out = (float*)d_out;

    float *h, *ob, *deg;
    half_t *xh, *hgh, *qkh, *atth, *hnh, *uph, *dnh, *Winh, *Wqkh, *Wlh, *Wrh, *upwh, *dnwh;
    int *starts, *pos; unsigned* adj;
    cudaGetSymbolAddress((void**)&h,   g_h);
    cudaGetSymbolAddress((void**)&ob,  g_out);
    cudaGetSymbolAddress((void**)&deg, g_deg);
    cudaGetSymbolAddress((void**)&starts, g_starts);
    cudaGetSymbolAddress((void**)&pos,    g_pos);
    cudaGetSymbolAddress((void**)&adj,    g_adj);
    cudaGetSymbolAddress((void**)&xh,   g_xh);
    cudaGetSymbolAddress((void**)&hgh,  g_hgh);
    cudaGetSymbolAddress((void**)&qkh,  g_qkh);
    cudaGetSymbolAddress((void**)&atth, g_atth);
    cudaGetSymbolAddress((void**)&hnh,  g_hnh);
    cudaGetSymbolAddress((void**)&uph,  g_uph);
    cudaGetSymbolAddress((void**)&dnh,  g_dnh);
    cudaGetSymbolAddress((void**)&Winh, g_Winh);
    cudaGetSymbolAddress((void**)&Wqkh, g_Wqkh);
    cudaGetSymbolAddress((void**)&Wlh,  g_Wlh);
    cudaGetSymbolAddress((void**)&Wrh,  g_Wrh);
    cudaGetSymbolAddress((void**)&upwh, g_upwh);
    cudaGetSymbolAddress((void**)&dnwh, g_dnwh);

    cudaFuncSetAttribute((const void*)gemm_h<128,false,false>,
                         cudaFuncAttributeMaxDynamicSharedMemorySize, H_SMEM_128);
    cudaFuncSetAttribute((const void*)gemm_h<128,false,true>,
                         cudaFuncAttributeMaxDynamicSharedMemorySize, H_SMEM_128);
    cudaFuncSetAttribute((const void*)gemm_h<128,true,false>,
                         cudaFuncAttributeMaxDynamicSharedMemorySize, H_SMEM_128);
    cudaFuncSetAttribute((const void*)gemm_h<64,false,true>,
                         cudaFuncAttributeMaxDynamicSharedMemorySize, H_SMEM_64);

    convert_k<<<NN*FF/1024, 256>>>(x, xh, NN*FF);
    convert_k<<<FF*HH/1024, 256>>>(W_in, Winh, FF*HH);
    clear_adj_k<<<(int)((ADJTOT + 255)/256), 256>>>(adj);

    // h = x @ W_in + b_in   (K=128)
    gemm_h<128,false,false><<<dim3(HH/128, NN/BM, 1), 256, H_SMEM_128>>>(
        xh, FF, 0, Winh, HH, 0, nullptr, nullptr, h, HH, 0, b_in, 0, FF, 0);

    starts_k  <<<NN/256, 256>>>(batch, starts);
    pos_self_k<<<NN/256, 256>>>(batch, starts, pos, adj);
    edge_k<<<EE/256, 256>>>(ei, batch, pos, adj);
    deg_k <<<NN/256, 256>>>(batch, pos, adj, deg);

    convert_k<<<LL*HH*HH/1024, 256>>>(Wqk, Wqkh, LL*HH*HH);
    convert_k<<<LL*HH*HH/1024, 256>>>(Wl, Wlh, LL*HH*HH);
    convert_k<<<LL*HH*HH/1024, 256>>>(Wr, Wrh, LL*HH*HH);
    convert_k<<<LL*GG*HG*HFG/1024, 256>>>(up_w, upwh, LL*GG*HG*HFG);
    convert_k<<<LL*GG*HFG*HG/1024, 256>>>(dn_w, dnwh, LL*GG*HFG*HG);

    // layer-0 gate (later layers fused into ln_res)
    gate_k<<<NN, 128>>>(h, deg, Wd, bd, hgh);

    for (int l = 0; l < LL; l++){
        // qk = sigmoid(hg@Wqk + bqk)  -> fp16 output
        gemm_h<128,false,true><<<dim3(HH/128, NN/BM, 1), 256, H_SMEM_128>>>(
            hgh, HH, 0, Wqkh + (size_t)l*HH*HH, HH, 0, nullptr, nullptr,
            qkh, HH, 0, bqk + l*HH, 0, HH, FLAG_SIG);
        attn_k<<<NN/8, 256>>>(qkh, hgh, adj, starts, batch, atth);
        // ob = att@Wl + hg@Wr + bl  (fp16 dual, fp32 out)
        gemm_h<128,true,false><<<dim3(HH/128, NN/BM, 1), 256, H_SMEM_128>>>(
            atth, HH, 0, Wlh + (size_t)l*HH*HH, HH, 0,
            hgh, Wrh + (size_t)l*HH*HH,
            ob, HH, 0, bl + l*HH, 0, HH, 0);
        l2ln_k<<<NN, 128>>>(ob, h, hnh, ln_g + l*HH, ln_b + l*HH);
        // grouped up (fp16): [N,64]@[64,256]  K=64 -> fp16 out
        gemm_h<128,false,true><<<dim3(HFG/128, NN/BM, GG), 256, H_SMEM_128>>>(
            hnh, HH, HG, upwh + (size_t)l*GG*HG*HFG, HFG, (long long)HG*HFG,
            nullptr, nullptr, uph, HFF, HFG, up_b + (size_t)l*GG*HFG, HFG, 64, 0);
        ln_up_k<<<NN*GG, 64>>>(uph, up_lg + l*HFG, up_lb + l*HFG);
        // grouped down (fp16): [N,256]@[256,64]  K=256 -> fp16 out
        gemm_h<64,false,true><<<dim3(1, NN/BM, GG), 256, H_SMEM_64>>>(
            uph, HFF, HFG, dnwh + (size_t)l*GG*HFG*HG, HG, (long long)HFG*HG,
            nullptr, nullptr, dnh, HH, HG, dn_b + (size_t)l*GG*HG, HG, 256, 0);
        // LN(64) + residual; layers 0,1 also emit next layer's gated hgh
        if (l + 1 < LL){
            ln_res_k<true><<<NN*GG, 64>>>(dnh, h, dn_lg + l*HG, dn_lb + l*HG,
                                          gamma + l*HH, deg,
                                          Wd + (l+1)*HH, bd + (l+1)*HH, hgh);
        } else {
            ln_res_k<false><<<NN*GG, 64>>>(dnh, h, dn_lg + l*HG, dn_lb + l*HG,
                                           gamma + l*HH, nullptr, nullptr, nullptr, nullptr);
        }
    }

    pool_k<<<dim3(BB, HH/128), 128>>>(h, starts, out);
}